// round 1
// baseline (speedup 1.0000x reference)
#include <cuda_runtime.h>
#include <math.h>

// Problem dims
#define Bb   8
#define Ss   4096
#define Dd   32
#define Nst  16
#define HIDn 128
#define Ll   64                 // chunk length
#define CPB  (Ss/Ll)            // 64 chunks per batch
#define NCHUNK (Bb*CPB)         // 512 chunks total
#define TOK  (Bb*Ss)            // 32768 tokens
#define OUT_ELEMS ((size_t)TOK*Dd*Dd)   // 33554432

// ---------------- scratch (device globals; no runtime allocation) ----------
__device__ float g_xp [TOK*Dd];        // x_proj         [token, d]
__device__ float g_a  [TOK*Nst];       // exp(dt*A)      [token, n]
__device__ float g_bd [TOK*Nst];       // dt*Bm          [token, n]
__device__ float g_c  [TOK*Nst];       // Cm             [token, n]
__device__ float g_P  [NCHUNK*Nst];    // chunk prod(a)
__device__ float g_sL [NCHUNK*Dd*Nst]; // chunk local end state (from 0)
__device__ float g_hin[NCHUNK*Dd*Nst]; // state entering each chunk
__device__ float g_hT [Bb*Dd*Nst];     // final state per batch
__device__ float g_Sx [Bb*Dd];         // sum_s x[b,s,d]
__device__ float g_Sxx[Bb];            // sum_{s,d} x^2
__device__ float g_weff[Dd];           // Wdt @ Wdtr
__device__ float g_c0;                 // bdt @ Wdtr

// ---------------- K0: tiny prep + zero accumulators -------------------------
__global__ void k0_prep(const float* __restrict__ Wdt,
                        const float* __restrict__ bdt,
                        const float* __restrict__ Wdtr)
{
    int tid = threadIdx.x;
    if (tid < Dd) {
        float s = 0.f;
        #pragma unroll
        for (int r = 0; r < Nst; r++) s += Wdt[tid*Nst + r] * Wdtr[r];
        g_weff[tid] = s;
        for (int b = 0; b < Bb; b++) g_Sx[b*Dd + tid] = 0.f;
    }
    if (tid == 32) {
        float s = 0.f;
        #pragma unroll
        for (int r = 0; r < Nst; r++) s += bdt[r] * Wdtr[r];
        g_c0 = s;
    }
    if (tid >= 40 && tid < 40 + Bb) g_Sxx[tid - 40] = 0.f;
}

// ---------------- K1: per-token projections (warp == token) -----------------
// block = 256 threads = 8 warps = 8 tokens; grid = 4096 blocks (block stays
// inside one batch since 4096 tokens/batch is a multiple of 8).
__global__ __launch_bounds__(256) void k1_proj(
    const float* __restrict__ x,   const float* __restrict__ A,
    const float* __restrict__ Win, const float* __restrict__ binp,
    const float* __restrict__ WB,  const float* __restrict__ WC)
{
    __shared__ float sWin[Dd*Dd], sWB[Dd*Nst], sWC[Dd*Nst];
    __shared__ float sweff[Dd], sA[Nst];
    __shared__ float sSx[Dd];
    __shared__ float sSxx;

    int tid = threadIdx.x;
    for (int i = tid; i < Dd*Dd;  i += 256) sWin[i] = Win[i];
    for (int i = tid; i < Dd*Nst; i += 256) { sWB[i] = WB[i]; sWC[i] = WC[i]; }
    if (tid < Dd)  { sweff[tid] = g_weff[tid]; sSx[tid] = 0.f; }
    if (tid < Nst) sA[tid] = A[tid];
    if (tid == 0)  sSxx = 0.f;
    __syncthreads();

    int warp = tid >> 5, lane = tid & 31;
    int token = blockIdx.x * 8 + warp;

    float xv = x[(size_t)token*Dd + lane];

    // x_proj[d=lane] = bin + sum_k x[k] * Win[k, lane]
    float xp = binp[lane];
    #pragma unroll
    for (int k = 0; k < Dd; k++) {
        float xk = __shfl_sync(0xffffffffu, xv, k);
        xp += xk * sWin[k*Dd + lane];
    }

    // dt = softplus( xp . weff + c0 )
    float part = xp * sweff[lane];
    #pragma unroll
    for (int m = 16; m >= 1; m >>= 1) part += __shfl_xor_sync(0xffffffffu, part, m);
    float zz = part + g_c0;
    float dt = fmaxf(zz, 0.f) + log1pf(expf(-fabsf(zz)));

    // lanes 0..15: Bm[n];  lanes 16..31: Cm[n]
    int ln = lane & 15;
    const float* Wsel = (lane < 16) ? sWB : sWC;
    float acc = 0.f;
    #pragma unroll
    for (int k = 0; k < Dd; k++) {
        float xpk = __shfl_sync(0xffffffffu, xp, k);
        acc += xpk * Wsel[k*Nst + ln];
    }

    g_xp[(size_t)token*Dd + lane] = xp;
    if (lane < 16) {
        g_a [(size_t)token*Nst + ln] = expf(dt * sA[ln]);
        g_bd[(size_t)token*Nst + ln] = dt * acc;
    } else {
        g_c [(size_t)token*Nst + ln] = acc;
    }

    // loss statistics
    atomicAdd(&sSx[lane], xv);
    float sq = xv * xv;
    #pragma unroll
    for (int m = 16; m >= 1; m >>= 1) sq += __shfl_xor_sync(0xffffffffu, sq, m);
    if (lane == 0) atomicAdd(&sSxx, sq);
    __syncthreads();

    int b = token >> 12;   // token / 4096
    if (tid < Dd)  atomicAdd(&g_Sx[b*Dd + tid], sSx[tid]);
    if (tid == 0)  atomicAdd(&g_Sxx[b], sSxx);
}

// ---------------- K2: per-chunk local scan (from zero) ----------------------
// block = 512 threads, one per (d, n); grid = NCHUNK.
__global__ __launch_bounds__(512) void k2_local(void)
{
    __shared__ float sa[Ll*Nst], sbd[Ll*Nst], sx[Ll*Dd];
    int chunk = blockIdx.x, tid = threadIdx.x;
    size_t t0 = (size_t)chunk * Ll;   // chunk = b*CPB + cl  ->  t0 = b*Ss + cl*Ll

    for (int i = tid; i < Ll*Nst; i += 512) {
        sa [i] = g_a [t0*Nst + i];
        sbd[i] = g_bd[t0*Nst + i];
    }
    for (int i = tid; i < Ll*Dd; i += 512) sx[i] = g_xp[t0*Dd + i];
    __syncthreads();

    int d = tid >> 4, n = tid & 15;
    float h = 0.f, p = 1.f;
    #pragma unroll 4
    for (int t = 0; t < Ll; t++) {
        float a = sa[t*Nst + n];
        h = a*h + sbd[t*Nst + n] * sx[t*Dd + d];
        p *= a;
    }
    g_sL[(size_t)chunk*512 + tid] = h;
    if (d == 0) g_P[chunk*Nst + n] = p;
}

// ---------------- K3: sequential cross-chunk combine ------------------------
__global__ __launch_bounds__(512) void k3_combine(void)
{
    int b = blockIdx.x, tid = threadIdx.x, n = tid & 15;
    float h = 0.f;
    for (int c = 0; c < CPB; c++) {
        int chunk = b*CPB + c;
        g_hin[(size_t)chunk*512 + tid] = h;
        h = g_P[chunk*Nst + n] * h + g_sL[(size_t)chunk*512 + tid];
    }
    g_hT[b*512 + tid] = h;
}

// ---------------- K4: replay with correct h_in, fused output write ----------
__global__ __launch_bounds__(512) void k4_output(
    const float* __restrict__ Wout, const float* __restrict__ bout,
    float* __restrict__ out)
{
    __shared__ float sa[Ll*Nst], sbd[Ll*Nst], sc[Ll*Nst], sx[Ll*Dd];
    int chunk = blockIdx.x, tid = threadIdx.x;
    size_t t0 = (size_t)chunk * Ll;

    for (int i = tid; i < Ll*Nst; i += 512) {
        sa [i] = g_a [t0*Nst + i];
        sbd[i] = g_bd[t0*Nst + i];
        sc [i] = g_c [t0*Nst + i];
    }
    for (int i = tid; i < Ll*Dd; i += 512) sx[i] = g_xp[t0*Dd + i];
    __syncthreads();

    int d = tid >> 4, n = tid & 15;
    float h  = g_hin[(size_t)chunk*512 + tid];
    float w0 = Wout[2*n],   w1 = Wout[2*n + 1];
    float b0 = bout[2*n],   b1 = bout[2*n + 1];
    float2* outv = (float2*)out;

    for (int t = 0; t < Ll; t++) {
        h = sa[t*Nst + n]*h + sbd[t*Nst + n]*sx[t*Dd + d];
        float y = sc[t*Nst + n] * h;
        #pragma unroll
        for (int m = 8; m >= 1; m >>= 1) y += __shfl_xor_sync(0xffffffffu, y, m);
        // out[token, d, :] = y * Wout + bout   (float2 per lane, fully coalesced)
        size_t ob = ((t0 + t)*(size_t)Dd + d)*16 + n;
        float2 v; v.x = y*w0 + b0; v.y = y*w1 + b1;
        outv[ob] = v;
    }
}

// ---------------- K5: MLP head + closed-form mi_loss ------------------------
__global__ __launch_bounds__(HIDn) void k5_loss(
    const float* __restrict__ Wd1, const float* __restrict__ bd1,
    const float* __restrict__ Wd2, const float* __restrict__ bd2,
    const float* __restrict__ Wd3, const float* __restrict__ bd3,
    float* __restrict__ out, long long out_size)
{
    __shared__ float hrep[Nst], z1[HIDn], z2[HIDn], uu[Dd];
    int tid = threadIdx.x;
    float total = 0.f;

    for (int b = 0; b < Bb; b++) {
        __syncthreads();
        if (tid < Nst) {
            float s = 0.f;
            #pragma unroll
            for (int d = 0; d < Dd; d++) s += g_hT[b*512 + d*16 + tid];
            hrep[tid] = s * (1.f/(float)Dd);
        }
        __syncthreads();
        {   // layer 1: 16 -> 128, relu
            float acc = bd1[tid];
            #pragma unroll
            for (int n = 0; n < Nst; n++) acc += hrep[n] * Wd1[n*HIDn + tid];
            z1[tid] = fmaxf(acc, 0.f);
        }
        __syncthreads();
        {   // layer 2: 128 -> 128, relu
            float acc = bd2[tid];
            for (int j = 0; j < HIDn; j++) acc += z1[j] * Wd2[j*HIDn + tid];
            z2[tid] = fmaxf(acc, 0.f);
        }
        __syncthreads();
        if (tid < Dd) {   // layer 3: 128 -> 32
            float acc = bd3[tid];
            for (int j = 0; j < HIDn; j++) acc += z2[j] * Wd3[j*Dd + tid];
            uu[tid] = acc;
        }
        __syncthreads();
        if (tid == 0) {
            // sum_s sum_d (u - x)^2 = S*|u|^2 - 2 u.Sx + Sxx
            float t1 = 0.f, t2 = 0.f;
            #pragma unroll
            for (int d = 0; d < Dd; d++) {
                t1 += uu[d]*uu[d];
                t2 += uu[d]*g_Sx[b*Dd + d];
            }
            total += (float)Ss * t1 - 2.f*t2 + g_Sxx[b];
        }
    }
    if (tid == 0 && out_size > (long long)OUT_ELEMS)
        out[out_size - 1] = total * (1.f/(float)(Bb*Ss));
}

// ---------------- launch -----------------------------------------------------
extern "C" void kernel_launch(void* const* d_in, const int* in_sizes, int n_in,
                              void* d_out, int out_size)
{
    const float* x    = (const float*)d_in[0];
    const float* A    = (const float*)d_in[1];
    const float* Win  = (const float*)d_in[2];
    const float* binp = (const float*)d_in[3];
    const float* Wdt  = (const float*)d_in[4];
    const float* bdt  = (const float*)d_in[5];
    const float* Wdtr = (const float*)d_in[6];
    const float* WB   = (const float*)d_in[7];
    const float* WC   = (const float*)d_in[8];
    const float* Wout = (const float*)d_in[9];
    const float* bout = (const float*)d_in[10];
    const float* Wd1  = (const float*)d_in[11];
    const float* bd1  = (const float*)d_in[12];
    const float* Wd2  = (const float*)d_in[13];
    const float* bd2  = (const float*)d_in[14];
    const float* Wd3  = (const float*)d_in[15];
    const float* bd3  = (const float*)d_in[16];
    float* out = (float*)d_out;

    k0_prep   <<<1, 64>>>(Wdt, bdt, Wdtr);
    k1_proj   <<<TOK/8, 256>>>(x, A, Win, binp, WB, WC);
    k2_local  <<<NCHUNK, 512>>>();
    k3_combine<<<Bb, 512>>>();
    k4_output <<<NCHUNK, 512>>>(Wout, bout, out);
    k5_loss   <<<1, HIDn>>>(Wd1, bd1, Wd2, bd2, Wd3, bd3, out, (long long)out_size);
}

// round 3
// speedup vs baseline: 1.2373x; 1.2373x over previous
#include <cuda_runtime.h>
#include <math.h>

// Problem dims
#define Bb   8
#define Ss   4096
#define Dd   32
#define Nst  16
#define HIDn 128
#define Ll   64                 // chunk length
#define CPB  (Ss/Ll)            // 64 chunks per batch
#define NCHUNK (Bb*CPB)         // 512 chunks total
#define TOK  (Bb*Ss)            // 32768 tokens
#define OUT_ELEMS ((size_t)TOK*Dd*Dd)   // 33554432

// ---------------- scratch (device globals; no runtime allocation) ----------
__device__ float g_xp [TOK*Dd];        // x_proj         [token, d]
__device__ float g_a  [TOK*Nst];       // exp(dt*A)      [token, n]
__device__ float g_bd [TOK*Nst];       // dt*Bm          [token, n]
__device__ float g_c  [TOK*Nst];       // Cm             [token, n]
__device__ float g_P  [NCHUNK*Nst];    // chunk prod(a)
__device__ float g_sL [NCHUNK*Dd*Nst]; // chunk local end state (from 0)
__device__ float g_hin[NCHUNK*Dd*Nst]; // state entering each chunk
__device__ float g_hT [Bb*Dd*Nst];     // final state per batch
__device__ float g_Sx [Bb*Dd];         // sum_s x[b,s,d]
__device__ float g_Sxx[Bb];            // sum_{s,d} x^2
__device__ float g_weff[Dd];           // Wdt @ Wdtr
__device__ float g_c0;                 // bdt @ Wdtr

// ---------------- K0: tiny prep + zero accumulators -------------------------
__global__ void k0_prep(const float* __restrict__ Wdt,
                        const float* __restrict__ bdt,
                        const float* __restrict__ Wdtr)
{
    int tid = threadIdx.x;
    if (tid < Dd) {
        float s = 0.f;
        #pragma unroll
        for (int r = 0; r < Nst; r++) s += Wdt[tid*Nst + r] * Wdtr[r];
        g_weff[tid] = s;
        for (int b = 0; b < Bb; b++) g_Sx[b*Dd + tid] = 0.f;
    }
    if (tid == 32) {
        float s = 0.f;
        #pragma unroll
        for (int r = 0; r < Nst; r++) s += bdt[r] * Wdtr[r];
        g_c0 = s;
    }
    if (tid >= 40 && tid < 40 + Bb) g_Sxx[tid - 40] = 0.f;
}

// ---------------- K1: per-token projections (warp == token) -----------------
__global__ __launch_bounds__(256) void k1_proj(
    const float* __restrict__ x,   const float* __restrict__ A,
    const float* __restrict__ Win, const float* __restrict__ binp,
    const float* __restrict__ WB,  const float* __restrict__ WC)
{
    __shared__ float sWin[Dd*Dd], sWB[Dd*Nst], sWC[Dd*Nst];
    __shared__ float sweff[Dd], sA[Nst];
    __shared__ float sSx[Dd];
    __shared__ float sSxx;

    int tid = threadIdx.x;
    for (int i = tid; i < Dd*Dd;  i += 256) sWin[i] = Win[i];
    for (int i = tid; i < Dd*Nst; i += 256) { sWB[i] = WB[i]; sWC[i] = WC[i]; }
    if (tid < Dd)  { sweff[tid] = g_weff[tid]; sSx[tid] = 0.f; }
    if (tid < Nst) sA[tid] = A[tid];
    if (tid == 0)  sSxx = 0.f;
    __syncthreads();

    int warp = tid >> 5, lane = tid & 31;
    int token = blockIdx.x * 8 + warp;

    float xv = x[(size_t)token*Dd + lane];

    // x_proj[d=lane] = bin + sum_k x[k] * Win[k, lane]
    float xp = binp[lane];
    #pragma unroll
    for (int k = 0; k < Dd; k++) {
        float xk = __shfl_sync(0xffffffffu, xv, k);
        xp += xk * sWin[k*Dd + lane];
    }

    // dt = softplus( xp . weff + c0 )
    float part = xp * sweff[lane];
    #pragma unroll
    for (int m = 16; m >= 1; m >>= 1) part += __shfl_xor_sync(0xffffffffu, part, m);
    float zz = part + g_c0;
    float dt = fmaxf(zz, 0.f) + log1pf(expf(-fabsf(zz)));

    // lanes 0..15: Bm[n];  lanes 16..31: Cm[n]
    int ln = lane & 15;
    const float* Wsel = (lane < 16) ? sWB : sWC;
    float acc = 0.f;
    #pragma unroll
    for (int k = 0; k < Dd; k++) {
        float xpk = __shfl_sync(0xffffffffu, xp, k);
        acc += xpk * Wsel[k*Nst + ln];
    }

    g_xp[(size_t)token*Dd + lane] = xp;
    if (lane < 16) {
        g_a [(size_t)token*Nst + ln] = expf(dt * sA[ln]);
        g_bd[(size_t)token*Nst + ln] = dt * acc;
    } else {
        g_c [(size_t)token*Nst + ln] = acc;
    }

    // loss statistics
    atomicAdd(&sSx[lane], xv);
    float sq = xv * xv;
    #pragma unroll
    for (int m = 16; m >= 1; m >>= 1) sq += __shfl_xor_sync(0xffffffffu, sq, m);
    if (lane == 0) atomicAdd(&sSxx, sq);
    __syncthreads();

    int b = token >> 12;
    if (tid < Dd)  atomicAdd(&g_Sx[b*Dd + tid], sSx[tid]);
    if (tid == 0)  atomicAdd(&g_Sxx[b], sSxx);
}

// ---------------- K2: per-chunk local scan (from zero) ----------------------
__global__ __launch_bounds__(512) void k2_local(void)
{
    __shared__ float sa[Ll*Nst], sbd[Ll*Nst], sx[Ll*Dd];
    int chunk = blockIdx.x, tid = threadIdx.x;
    size_t t0 = (size_t)chunk * Ll;

    for (int i = tid; i < Ll*Nst; i += 512) {
        sa [i] = g_a [t0*Nst + i];
        sbd[i] = g_bd[t0*Nst + i];
    }
    for (int i = tid; i < Ll*Dd; i += 512) sx[i] = g_xp[t0*Dd + i];
    __syncthreads();

    int d = tid >> 4, n = tid & 15;
    float h = 0.f, p = 1.f;
    #pragma unroll 4
    for (int t = 0; t < Ll; t++) {
        float a = sa[t*Nst + n];
        h = a*h + sbd[t*Nst + n] * sx[t*Dd + d];
        p *= a;
    }
    g_sL[(size_t)chunk*512 + tid] = h;
    if (d == 0) g_P[chunk*Nst + n] = p;
}

// ---------------- K3: cross-chunk combine, MLP=8 prefetch -------------------
// grid = Bb*8 blocks (batch x d-group of 4), block = 64 threads (4 d x 16 n).
__global__ __launch_bounds__(64) void k3_combine(void)
{
    int b   = blockIdx.x >> 3;
    int dg  = blockIdx.x & 7;
    int tid = threadIdx.x;
    int n   = tid & 15;
    int d   = dg*4 + (tid >> 4);
    int off = d*Nst + n;           // 0..511

    float h = 0.f;
    #pragma unroll
    for (int cb = 0; cb < 8; cb++) {
        float lp[8], ls[8];
        #pragma unroll
        for (int j = 0; j < 8; j++) {
            int chunk = b*CPB + cb*8 + j;
            lp[j] = g_P [chunk*Nst + n];
            ls[j] = g_sL[(size_t)chunk*512 + off];
        }
        #pragma unroll
        for (int j = 0; j < 8; j++) {
            int chunk = b*CPB + cb*8 + j;
            g_hin[(size_t)chunk*512 + off] = h;
            h = lp[j]*h + ls[j];
        }
    }
    g_hT[b*512 + off] = h;
}

// ---------------- K4: replay scan -> smem y; then pure streaming store ------
__global__ __launch_bounds__(512) void k4_output(
    const float* __restrict__ Wout, const float* __restrict__ bout,
    float* __restrict__ out)
{
    __shared__ float sa[Ll*Nst], sbd[Ll*Nst], sc[Ll*Nst], sx[Ll*Dd];
    __shared__ float sy[Ll*Dd];
    int chunk = blockIdx.x, tid = threadIdx.x;
    size_t t0 = (size_t)chunk * Ll;

    for (int i = tid; i < Ll*Nst; i += 512) {
        sa [i] = g_a [t0*Nst + i];
        sbd[i] = g_bd[t0*Nst + i];
        sc [i] = g_c [t0*Nst + i];
    }
    for (int i = tid; i < Ll*Dd; i += 512) sx[i] = g_xp[t0*Dd + i];
    __syncthreads();

    // ---- phase 1: scan, reduce y over n into smem ----
    {
        int d = tid >> 4, n = tid & 15;
        float h = g_hin[(size_t)chunk*512 + tid];
        for (int t = 0; t < Ll; t++) {
            h = sa[t*Nst + n]*h + sbd[t*Nst + n]*sx[t*Dd + d];
            float y = sc[t*Nst + n] * h;
            #pragma unroll
            for (int m = 8; m >= 1; m >>= 1) y += __shfl_xor_sync(0xffffffffu, y, m);
            if (n == 0) sy[t*Dd + d] = y;
        }
    }
    __syncthreads();

    // ---- phase 2: streaming rank-1 expansion, float4 stores ----
    // thread -> fixed (d, q); t varies. 256 float4 per token.
    {
        int q     = tid & 7;            // float4 column (covers 4 of 32 outs)
        int dd    = (tid >> 3) & 31;    // d
        int tbase = tid >> 8;           // 0 or 1
        float4 w4 = ((const float4*)Wout)[q];
        float4 b4 = ((const float4*)bout)[q];
        float4* outp = (float4*)out + t0*256 + (size_t)tbase*256 + dd*8 + q;
        const float* syp = &sy[tbase*Dd + dd];
        #pragma unroll
        for (int k = 0; k < 32; k++) {
            float y = syp[k*2*Dd];
            float4 v;
            v.x = fmaf(y, w4.x, b4.x);
            v.y = fmaf(y, w4.y, b4.y);
            v.z = fmaf(y, w4.z, b4.z);
            v.w = fmaf(y, w4.w, b4.w);
            __stcs(outp + (size_t)k*512, v);
        }
    }
}

// ---------------- K5: MLP head + closed-form mi_loss ------------------------
__global__ __launch_bounds__(HIDn) void k5_loss(
    const float* __restrict__ Wd1, const float* __restrict__ bd1,
    const float* __restrict__ Wd2, const float* __restrict__ bd2,
    const float* __restrict__ Wd3, const float* __restrict__ bd3,
    float* __restrict__ out, long long out_size)
{
    __shared__ float hrep[Nst], z1[HIDn], z2[HIDn], uu[Dd];
    int tid = threadIdx.x;
    float total = 0.f;

    for (int b = 0; b < Bb; b++) {
        __syncthreads();
        if (tid < Nst) {
            float s = 0.f;
            #pragma unroll
            for (int d = 0; d < Dd; d++) s += g_hT[b*512 + d*16 + tid];
            hrep[tid] = s * (1.f/(float)Dd);
        }
        __syncthreads();
        {
            float acc = bd1[tid];
            #pragma unroll
            for (int n = 0; n < Nst; n++) acc += hrep[n] * Wd1[n*HIDn + tid];
            z1[tid] = fmaxf(acc, 0.f);
        }
        __syncthreads();
        {
            float acc = bd2[tid];
            for (int j = 0; j < HIDn; j++) acc += z1[j] * Wd2[j*HIDn + tid];
            z2[tid] = fmaxf(acc, 0.f);
        }
        __syncthreads();
        if (tid < Dd) {
            float acc = bd3[tid];
            for (int j = 0; j < HIDn; j++) acc += z2[j] * Wd3[j*Dd + tid];
            uu[tid] = acc;
        }
        __syncthreads();
        if (tid == 0) {
            float t1 = 0.f, t2 = 0.f;
            #pragma unroll
            for (int d = 0; d < Dd; d++) {
                t1 += uu[d]*uu[d];
                t2 += uu[d]*g_Sx[b*Dd + d];
            }
            total += (float)Ss * t1 - 2.f*t2 + g_Sxx[b];
        }
    }
    if (tid == 0 && out_size > (long long)OUT_ELEMS)
        out[out_size - 1] = total * (1.f/(float)(Bb*Ss));
}

// ---------------- launch -----------------------------------------------------
extern "C" void kernel_launch(void* const* d_in, const int* in_sizes, int n_in,
                              void* d_out, int out_size)
{
    const float* x    = (const float*)d_in[0];
    const float* A    = (const float*)d_in[1];
    const float* Win  = (const float*)d_in[2];
    const float* binp = (const float*)d_in[3];
    const float* Wdt  = (const float*)d_in[4];
    const float* bdt  = (const float*)d_in[5];
    const float* Wdtr = (const float*)d_in[6];
    const float* WB   = (const float*)d_in[7];
    const float* WC   = (const float*)d_in[8];
    const float* Wout = (const float*)d_in[9];
    const float* bout = (const float*)d_in[10];
    const float* Wd1  = (const float*)d_in[11];
    const float* bd1  = (const float*)d_in[12];
    const float* Wd2  = (const float*)d_in[13];
    const float* bd2  = (const float*)d_in[14];
    const float* Wd3  = (const float*)d_in[15];
    const float* bd3  = (const float*)d_in[16];
    float* out = (float*)d_out;

    k0_prep   <<<1, 64>>>(Wdt, bdt, Wdtr);
    k1_proj   <<<TOK/8, 256>>>(x, A, Win, binp, WB, WC);
    k2_local  <<<NCHUNK, 512>>>();
    k3_combine<<<Bb*8, 64>>>();
    k4_output <<<NCHUNK, 512>>>(Wout, bout, out);
    k5_loss   <<<1, HIDn>>>(Wd1, bd1, Wd2, bd2, Wd3, bd3, out, (long long)out_size);
}

// round 4
// speedup vs baseline: 1.9582x; 1.5827x over previous
#include <cuda_runtime.h>
#include <math.h>

// Problem dims
#define Bb   8
#define Ss   4096
#define Dd   32
#define Nst  16
#define HIDn 128
#define Ll   64
#define CPB  64                  // chunks per batch
#define NCHUNK 512               // total chunks
#define NGRP 8                   // groups per batch
#define GL   8                   // chunks per group
#define TOK  32768
#define OUT_ELEMS ((size_t)TOK*Dd*Dd)   // 33554432

// ---------------- scratch ----------------------------------------------------
__device__ float g_xp [TOK*Dd];
__device__ float g_a  [TOK*Nst];
__device__ float g_bd [TOK*Nst];
__device__ float g_c  [TOK*Nst];
__device__ float g_P  [NCHUNK*Nst];
__device__ float g_sL [NCHUNK*512];
__device__ float g_hinL[NCHUNK*512];        // group-local entering state
__device__ float g_gend[Bb*NGRP*512];       // group end state (from 0)
__device__ float g_Hg  [Bb*NGRP*512];       // state entering each group
__device__ float g_Plp [Bb*NGRP*GL*Nst];    // in-group prefix products
__device__ float g_Pg  [Bb*NGRP*Nst];       // group total products
__device__ float g_hT  [Bb*512];
__device__ float g_y   [TOK*Dd];
__device__ float g_Sx  [Bb*Dd];
__device__ float g_Sxx [Bb];
__device__ float g_weff[Dd];
__device__ float g_c0;
__device__ float g_loss;

// ---------------- K0: prep ---------------------------------------------------
__global__ void k0_prep(const float* __restrict__ Wdt,
                        const float* __restrict__ bdt,
                        const float* __restrict__ Wdtr)
{
    int tid = threadIdx.x;
    if (tid < Dd) {
        float s = 0.f;
        #pragma unroll
        for (int r = 0; r < Nst; r++) s += Wdt[tid*Nst + r] * Wdtr[r];
        g_weff[tid] = s;
        for (int b = 0; b < Bb; b++) g_Sx[b*Dd + tid] = 0.f;
    }
    if (tid == 32) {
        float s = 0.f;
        #pragma unroll
        for (int r = 0; r < Nst; r++) s += bdt[r] * Wdtr[r];
        g_c0 = s;
    }
    if (tid >= 40 && tid < 40 + Bb) g_Sxx[tid - 40] = 0.f;
    if (tid == 48) g_loss = 0.f;
}

// ---------------- K1: per-token projections ----------------------------------
__global__ __launch_bounds__(256) void k1_proj(
    const float* __restrict__ x,   const float* __restrict__ A,
    const float* __restrict__ Win, const float* __restrict__ binp,
    const float* __restrict__ WB,  const float* __restrict__ WC)
{
    __shared__ float sWin[Dd*Dd], sWB[Dd*Nst], sWC[Dd*Nst];
    __shared__ float sweff[Dd], sA[Nst];
    __shared__ float sSx[Dd];
    __shared__ float sSxx;

    int tid = threadIdx.x;
    for (int i = tid; i < Dd*Dd;  i += 256) sWin[i] = Win[i];
    for (int i = tid; i < Dd*Nst; i += 256) { sWB[i] = WB[i]; sWC[i] = WC[i]; }
    if (tid < Dd)  { sweff[tid] = g_weff[tid]; sSx[tid] = 0.f; }
    if (tid < Nst) sA[tid] = A[tid];
    if (tid == 0)  sSxx = 0.f;
    __syncthreads();

    int warp = tid >> 5, lane = tid & 31;
    int token = blockIdx.x * 8 + warp;

    float xv = x[(size_t)token*Dd + lane];

    float xp = binp[lane];
    #pragma unroll
    for (int k = 0; k < Dd; k++) {
        float xk = __shfl_sync(0xffffffffu, xv, k);
        xp += xk * sWin[k*Dd + lane];
    }

    float part = xp * sweff[lane];
    #pragma unroll
    for (int m = 16; m >= 1; m >>= 1) part += __shfl_xor_sync(0xffffffffu, part, m);
    float zz = part + g_c0;
    float dt = fmaxf(zz, 0.f) + log1pf(expf(-fabsf(zz)));

    int ln = lane & 15;
    const float* Wsel = (lane < 16) ? sWB : sWC;
    float acc = 0.f;
    #pragma unroll
    for (int k = 0; k < Dd; k++) {
        float xpk = __shfl_sync(0xffffffffu, xp, k);
        acc += xpk * Wsel[k*Nst + ln];
    }

    g_xp[(size_t)token*Dd + lane] = xp;
    if (lane < 16) {
        g_a [(size_t)token*Nst + ln] = expf(dt * sA[ln]);
        g_bd[(size_t)token*Nst + ln] = dt * acc;
    } else {
        g_c [(size_t)token*Nst + ln] = acc;
    }

    atomicAdd(&sSx[lane], xv);
    float sq = xv * xv;
    #pragma unroll
    for (int m = 16; m >= 1; m >>= 1) sq += __shfl_xor_sync(0xffffffffu, sq, m);
    if (lane == 0) atomicAdd(&sSxx, sq);
    __syncthreads();

    int b = token >> 12;
    if (tid < Dd)  atomicAdd(&g_Sx[b*Dd + tid], sSx[tid]);
    if (tid == 0)  atomicAdd(&g_Sxx[b], sSxx);
}

// ---------------- K2: warp-per-chunk local scan, h[16] in regs ---------------
// block = 64 threads = 2 warps = 2 chunks. lane = d. grid = 256.
__global__ __launch_bounds__(64) void k2_local(void)
{
    // per chunk: a 256 f4, bd 256 f4, x 512 f4 -> 1024 f4 = 16KB; x2 = 32KB
    __shared__ float4 s4[2*1024];
    int tid = threadIdx.x;
    int chunk0 = blockIdx.x * 2;

    for (int cc = 0; cc < 2; cc++) {
        int ch = chunk0 + cc;
        const float4* pa = (const float4*)g_a  + (size_t)ch*256;
        const float4* pb = (const float4*)g_bd + (size_t)ch*256;
        const float4* px = (const float4*)g_xp + (size_t)ch*512;
        float4* s = s4 + cc*1024;
        for (int i = tid; i < 256; i += 64) { s[i] = pa[i]; s[256+i] = pb[i]; }
        for (int i = tid; i < 512; i += 64) s[512+i] = px[i];
    }
    __syncthreads();

    int warp = tid >> 5, lane = tid & 31;
    int ch = chunk0 + warp;
    const float4* s  = s4 + warp*1024;
    const float*  sa = (const float*)s;
    const float*  sx = (const float*)(s + 512);
    int nl = lane & 15;

    float h[16];
    #pragma unroll
    for (int n = 0; n < 16; n++) h[n] = 0.f;
    float p = 1.f;

    #pragma unroll 2
    for (int t = 0; t < Ll; t++) {
        float av[16], bv[16];
        *(float4*)&av[0]  = s[t*4+0];   *(float4*)&av[4]  = s[t*4+1];
        *(float4*)&av[8]  = s[t*4+2];   *(float4*)&av[12] = s[t*4+3];
        *(float4*)&bv[0]  = s[256+t*4+0]; *(float4*)&bv[4]  = s[256+t*4+1];
        *(float4*)&bv[8]  = s[256+t*4+2]; *(float4*)&bv[12] = s[256+t*4+3];
        float xv = sx[t*32 + lane];
        float pa = sa[t*16 + nl];
        #pragma unroll
        for (int n = 0; n < 16; n++) h[n] = fmaf(av[n], h[n], bv[n]*xv);
        p *= pa;
    }

    float4* outL = (float4*)g_sL + (size_t)ch*128 + lane*4;
    outL[0] = make_float4(h[0],h[1],h[2],h[3]);
    outL[1] = make_float4(h[4],h[5],h[6],h[7]);
    outL[2] = make_float4(h[8],h[9],h[10],h[11]);
    outL[3] = make_float4(h[12],h[13],h[14],h[15]);
    if (lane < 16) g_P[ch*Nst + lane] = p;
}

// ---------------- K3a: group-local combine (8 chunks, batched loads) --------
__global__ __launch_bounds__(512) void k3a(void)
{
    int bg  = blockIdx.x;            // b*8+g; first chunk = bg*8
    int off = threadIdx.x;
    int n   = off & 15;
    int c0  = bg * GL;

    float lp[GL], ls[GL];
    #pragma unroll
    for (int j = 0; j < GL; j++) {
        lp[j] = g_P [(c0+j)*Nst + n];
        ls[j] = g_sL[(size_t)(c0+j)*512 + off];
    }
    float h = 0.f, pl = 1.f;
    #pragma unroll
    for (int j = 0; j < GL; j++) {
        g_hinL[(size_t)(c0+j)*512 + off] = h;
        if (off < 16) g_Plp[(bg*GL + j)*Nst + n] = pl;
        h  = fmaf(lp[j], h, ls[j]);
        pl *= lp[j];
    }
    g_gend[bg*512 + off] = h;
    if (off < 16) g_Pg[bg*Nst + n] = pl;
}

// ---------------- K3b: cross-group combine (8 steps, batched loads) ---------
__global__ __launch_bounds__(512) void k3b(void)
{
    int b = blockIdx.x, off = threadIdx.x, n = off & 15;
    float pg[NGRP], ge[NGRP];
    #pragma unroll
    for (int g = 0; g < NGRP; g++) {
        pg[g] = g_Pg  [(b*NGRP+g)*Nst + n];
        ge[g] = g_gend[(b*NGRP+g)*512 + off];
    }
    float h = 0.f;
    #pragma unroll
    for (int g = 0; g < NGRP; g++) {
        g_Hg[(b*NGRP+g)*512 + off] = h;
        h = fmaf(pg[g], h, ge[g]);
    }
    g_hT[b*512 + off] = h;
}

// ---------------- K4a: warp-per-chunk replay scan -> g_y --------------------
// block = 64 threads = 2 warps = 2 chunks. lane = d. grid = 256.
__global__ __launch_bounds__(64) void k4a(void)
{
    // per chunk: a 256, bd 256, c 256, x 512 -> 1280 f4 = 20KB; x2 = 40KB
    __shared__ float4 s4[2*1280];
    int tid = threadIdx.x;
    int chunk0 = blockIdx.x * 2;

    for (int cc = 0; cc < 2; cc++) {
        int ch = chunk0 + cc;
        const float4* pa = (const float4*)g_a  + (size_t)ch*256;
        const float4* pb = (const float4*)g_bd + (size_t)ch*256;
        const float4* pc = (const float4*)g_c  + (size_t)ch*256;
        const float4* px = (const float4*)g_xp + (size_t)ch*512;
        float4* s = s4 + cc*1280;
        for (int i = tid; i < 256; i += 64) { s[i] = pa[i]; s[256+i] = pb[i]; s[512+i] = pc[i]; }
        for (int i = tid; i < 512; i += 64) s[768+i] = px[i];
    }
    __syncthreads();

    int warp = tid >> 5, lane = tid & 31;
    int ch = chunk0 + warp;
    int bg = ch >> 3, j = ch & 7;
    const float4* s  = s4 + warp*1280;
    const float*  sx = (const float*)(s + 768);

    // h_in = hinL + Plp * Hg   (linear-scan composition)
    float h[16];
    {
        const float4* hin = (const float4*)g_hinL + (size_t)ch*128 + lane*4;
        const float4* hg  = (const float4*)g_Hg   + (size_t)bg*128 + lane*4;
        const float4* plp = (const float4*)g_Plp  + (bg*GL + j)*4;
        #pragma unroll
        for (int k = 0; k < 4; k++) {
            float4 hi = hin[k], hgv = hg[k], pl = plp[k];
            h[k*4+0] = fmaf(pl.x, hgv.x, hi.x);
            h[k*4+1] = fmaf(pl.y, hgv.y, hi.y);
            h[k*4+2] = fmaf(pl.z, hgv.z, hi.z);
            h[k*4+3] = fmaf(pl.w, hgv.w, hi.w);
        }
    }

    float* yout = g_y + (size_t)ch*Ll*Dd + lane;
    for (int t = 0; t < Ll; t++) {
        float av[16], bv[16], cv[16];
        *(float4*)&av[0]  = s[t*4+0];     *(float4*)&av[4]  = s[t*4+1];
        *(float4*)&av[8]  = s[t*4+2];     *(float4*)&av[12] = s[t*4+3];
        *(float4*)&bv[0]  = s[256+t*4+0]; *(float4*)&bv[4]  = s[256+t*4+1];
        *(float4*)&bv[8]  = s[256+t*4+2]; *(float4*)&bv[12] = s[256+t*4+3];
        *(float4*)&cv[0]  = s[512+t*4+0]; *(float4*)&cv[4]  = s[512+t*4+1];
        *(float4*)&cv[8]  = s[512+t*4+2]; *(float4*)&cv[12] = s[512+t*4+3];
        float xv = sx[t*32 + lane];
        float y0 = 0.f, y1 = 0.f, y2 = 0.f, y3 = 0.f;
        #pragma unroll
        for (int n = 0; n < 16; n += 4) {
            h[n+0] = fmaf(av[n+0], h[n+0], bv[n+0]*xv); y0 = fmaf(cv[n+0], h[n+0], y0);
            h[n+1] = fmaf(av[n+1], h[n+1], bv[n+1]*xv); y1 = fmaf(cv[n+1], h[n+1], y1);
            h[n+2] = fmaf(av[n+2], h[n+2], bv[n+2]*xv); y2 = fmaf(cv[n+2], h[n+2], y2);
            h[n+3] = fmaf(av[n+3], h[n+3], bv[n+3]*xv); y3 = fmaf(cv[n+3], h[n+3], y3);
        }
        yout[t*Dd] = (y0 + y1) + (y2 + y3);
    }
}

// ---------------- K4b: pure streaming rank-1 expansion ----------------------
// block = 256 threads handles 8 tokens = 256 (t,d) rows = 2048 float4 contiguous.
__global__ __launch_bounds__(256) void k4b(
    const float* __restrict__ Wout, const float* __restrict__ bout,
    float* __restrict__ out)
{
    __shared__ float  sy[256];
    __shared__ float4 sw[8], sb[8];
    int tid = threadIdx.x;
    sy[tid] = g_y[(size_t)blockIdx.x*256 + tid];
    if (tid < 8)            sw[tid]   = ((const float4*)Wout)[tid];
    else if (tid < 16)      sb[tid-8] = ((const float4*)bout)[tid-8];
    __syncthreads();

    int q = tid & 7, r0 = tid >> 3;
    float4 w4 = sw[q], b4 = sb[q];
    float4* o = (float4*)out + (size_t)blockIdx.x*2048;
    #pragma unroll
    for (int k = 0; k < 8; k++) {
        int r = r0 + k*32;
        float y = sy[r];
        float4 v;
        v.x = fmaf(y, w4.x, b4.x);
        v.y = fmaf(y, w4.y, b4.y);
        v.z = fmaf(y, w4.z, b4.z);
        v.w = fmaf(y, w4.w, b4.w);
        __stcs(&o[r*8 + q], v);
    }
}

// ---------------- K5: per-batch MLP loss (8 blocks) -------------------------
__global__ __launch_bounds__(HIDn) void k5_loss(
    const float* __restrict__ Wd1, const float* __restrict__ bd1,
    const float* __restrict__ Wd2, const float* __restrict__ bd2,
    const float* __restrict__ Wd3, const float* __restrict__ bd3)
{
    __shared__ float hrep[Nst], z1[HIDn], z2[HIDn], uu[Dd];
    int b = blockIdx.x, tid = threadIdx.x;

    if (tid < Nst) {
        float s = 0.f;
        #pragma unroll
        for (int d = 0; d < Dd; d++) s += g_hT[b*512 + d*Nst + tid];
        hrep[tid] = s * (1.f/(float)Dd);
    }
    __syncthreads();
    {
        float acc = bd1[tid];
        #pragma unroll
        for (int n = 0; n < Nst; n++) acc += hrep[n] * Wd1[n*HIDn + tid];
        z1[tid] = fmaxf(acc, 0.f);
    }
    __syncthreads();
    {
        float acc = bd2[tid];
        #pragma unroll 8
        for (int j = 0; j < HIDn; j++) acc += z1[j] * Wd2[j*HIDn + tid];
        z2[tid] = fmaxf(acc, 0.f);
    }
    __syncthreads();
    if (tid < Dd) {
        float acc = bd3[tid];
        #pragma unroll 8
        for (int j = 0; j < HIDn; j++) acc += z2[j] * Wd3[j*Dd + tid];
        uu[tid] = acc;
    }
    __syncthreads();
    if (tid == 0) {
        float t1 = 0.f, t2 = 0.f;
        #pragma unroll
        for (int d = 0; d < Dd; d++) {
            t1 += uu[d]*uu[d];
            t2 += uu[d]*g_Sx[b*Dd + d];
        }
        atomicAdd(&g_loss, (float)Ss * t1 - 2.f*t2 + g_Sxx[b]);
    }
}

// ---------------- K6: write scalar loss -------------------------------------
__global__ void k6_write(float* __restrict__ out, long long out_size)
{
    if (out_size > (long long)OUT_ELEMS)
        out[out_size - 1] = g_loss * (1.f/(float)(Bb*Ss));
}

// ---------------- launch -----------------------------------------------------
extern "C" void kernel_launch(void* const* d_in, const int* in_sizes, int n_in,
                              void* d_out, int out_size)
{
    const float* x    = (const float*)d_in[0];
    const float* A    = (const float*)d_in[1];
    const float* Win  = (const float*)d_in[2];
    const float* binp = (const float*)d_in[3];
    const float* Wdt  = (const float*)d_in[4];
    const float* bdt  = (const float*)d_in[5];
    const float* Wdtr = (const float*)d_in[6];
    const float* WB   = (const float*)d_in[7];
    const float* WC   = (const float*)d_in[8];
    const float* Wout = (const float*)d_in[9];
    const float* bout = (const float*)d_in[10];
    const float* Wd1  = (const float*)d_in[11];
    const float* bd1  = (const float*)d_in[12];
    const float* Wd2  = (const float*)d_in[13];
    const float* bd2  = (const float*)d_in[14];
    const float* Wd3  = (const float*)d_in[15];
    const float* bd3  = (const float*)d_in[16];
    float* out = (float*)d_out;

    k0_prep <<<1, 64>>>(Wdt, bdt, Wdtr);
    k1_proj <<<TOK/8, 256>>>(x, A, Win, binp, WB, WC);
    k2_local<<<NCHUNK/2, 64>>>();
    k3a     <<<Bb*NGRP, 512>>>();
    k3b     <<<Bb, 512>>>();
    k4a     <<<NCHUNK/2, 64>>>();
    k4b     <<<TOK/8, 256>>>(Wout, bout, out);
    k5_loss <<<Bb, HIDn>>>(Wd1, bd1, Wd2, bd2, Wd3, bd3);
    k6_write<<<1, 1>>>(out, (long long)out_size);
}

// round 5
// speedup vs baseline: 2.2399x; 1.1439x over previous
#include <cuda_runtime.h>
#include <math.h>

// Problem dims
#define Bb   8
#define Ss   4096
#define Dd   32
#define Nst  16
#define HIDn 128
#define Ll   64
#define CPB  64                  // chunks per batch
#define NCHUNK 512               // total chunks
#define NGRP 8                   // groups per batch
#define GL   8                   // chunks per group
#define TOK  32768
#define OUT_ELEMS ((size_t)TOK*Dd*Dd)   // 33554432

// ---------------- scratch ----------------------------------------------------
__device__ float g_xp  [TOK*Dd];
__device__ float g_a   [TOK*Nst];
__device__ float g_bd  [TOK*Nst];
__device__ float g_c   [TOK*Nst];
__device__ float g_P   [NCHUNK*Nst];
__device__ float g_sL  [NCHUNK*512];
__device__ float g_yloc[TOK*Dd];            // local y (h from 0)
__device__ float g_cpi [TOK*Nst];           // c_t * prefixprod_t
__device__ float g_hinL[NCHUNK*512];        // group-local entering state
__device__ float g_gend[Bb*NGRP*512];       // group end state (from 0)
__device__ float g_Hg  [Bb*NGRP*512];       // state entering each group
__device__ float g_Plp [Bb*NGRP*GL*Nst];    // in-group prefix products
__device__ float g_Pg  [Bb*NGRP*Nst];       // group total products
__device__ float g_Sx  [Bb*Dd];
__device__ float g_Sxx [Bb];
__device__ float g_weff[Dd];
__device__ float g_c0;
__device__ float g_lossB[Bb];

// ---------------- K0: prep ---------------------------------------------------
__global__ void k0_prep(const float* __restrict__ Wdt,
                        const float* __restrict__ bdt,
                        const float* __restrict__ Wdtr)
{
    int tid = threadIdx.x;
    if (tid < Dd) {
        float s = 0.f;
        #pragma unroll
        for (int r = 0; r < Nst; r++) s += Wdt[tid*Nst + r] * Wdtr[r];
        g_weff[tid] = s;
        for (int b = 0; b < Bb; b++) g_Sx[b*Dd + tid] = 0.f;
    }
    if (tid == 32) {
        float s = 0.f;
        #pragma unroll
        for (int r = 0; r < Nst; r++) s += bdt[r] * Wdtr[r];
        g_c0 = s;
    }
    if (tid >= 40 && tid < 40 + Bb) g_Sxx[tid - 40] = 0.f;
}

// ---------------- K1: per-token projections ----------------------------------
__global__ __launch_bounds__(256) void k1_proj(
    const float* __restrict__ x,   const float* __restrict__ A,
    const float* __restrict__ Win, const float* __restrict__ binp,
    const float* __restrict__ WB,  const float* __restrict__ WC)
{
    __shared__ float sWin[Dd*Dd], sWB[Dd*Nst], sWC[Dd*Nst];
    __shared__ float sweff[Dd], sA[Nst];
    __shared__ float sSx[Dd];
    __shared__ float sSxx;

    int tid = threadIdx.x;
    for (int i = tid; i < Dd*Dd;  i += 256) sWin[i] = Win[i];
    for (int i = tid; i < Dd*Nst; i += 256) { sWB[i] = WB[i]; sWC[i] = WC[i]; }
    if (tid < Dd)  { sweff[tid] = g_weff[tid]; sSx[tid] = 0.f; }
    if (tid < Nst) sA[tid] = A[tid];
    if (tid == 0)  sSxx = 0.f;
    __syncthreads();

    int warp = tid >> 5, lane = tid & 31;
    int token = blockIdx.x * 8 + warp;

    float xv = x[(size_t)token*Dd + lane];

    float xp = binp[lane];
    #pragma unroll
    for (int k = 0; k < Dd; k++) {
        float xk = __shfl_sync(0xffffffffu, xv, k);
        xp += xk * sWin[k*Dd + lane];
    }

    float part = xp * sweff[lane];
    #pragma unroll
    for (int m = 16; m >= 1; m >>= 1) part += __shfl_xor_sync(0xffffffffu, part, m);
    float zz = part + g_c0;
    float dt = fmaxf(zz, 0.f) + log1pf(expf(-fabsf(zz)));

    int ln = lane & 15;
    const float* Wsel = (lane < 16) ? sWB : sWC;
    float acc = 0.f;
    #pragma unroll
    for (int k = 0; k < Dd; k++) {
        float xpk = __shfl_sync(0xffffffffu, xp, k);
        acc += xpk * Wsel[k*Nst + ln];
    }

    g_xp[(size_t)token*Dd + lane] = xp;
    if (lane < 16) {
        g_a [(size_t)token*Nst + ln] = expf(dt * sA[ln]);
        g_bd[(size_t)token*Nst + ln] = dt * acc;
    } else {
        g_c [(size_t)token*Nst + ln] = acc;
    }

    atomicAdd(&sSx[lane], xv);
    float sq = xv * xv;
    #pragma unroll
    for (int m = 16; m >= 1; m >>= 1) sq += __shfl_xor_sync(0xffffffffu, sq, m);
    if (lane == 0) atomicAdd(&sSxx, sq);
    __syncthreads();

    int b = token >> 12;
    if (tid < Dd)  atomicAdd(&g_Sx[b*Dd + tid], sSx[tid]);
    if (tid == 0)  atomicAdd(&g_Sxx[b], sSxx);
}

// ---------------- K2: warp-per-chunk scan; emits sL, P, y_local, cpi --------
// block = 64 threads = 2 warps = 2 chunks; lane = d; grid = 256.
__global__ __launch_bounds__(64) void k2_scan(void)
{
    // per chunk: a 256 f4, bd 256 f4, c 256 f4, x 512 f4 = 1280 f4 = 20KB; x2
    __shared__ float4 s4[2*1280];
    int tid = threadIdx.x;
    int chunk0 = blockIdx.x * 2;

    for (int cc = 0; cc < 2; cc++) {
        int ch = chunk0 + cc;
        const float4* pa = (const float4*)g_a  + (size_t)ch*256;
        const float4* pb = (const float4*)g_bd + (size_t)ch*256;
        const float4* pc = (const float4*)g_c  + (size_t)ch*256;
        const float4* px = (const float4*)g_xp + (size_t)ch*512;
        float4* s = s4 + cc*1280;
        for (int i = tid; i < 256; i += 64) { s[i] = pa[i]; s[256+i] = pb[i]; s[512+i] = pc[i]; }
        for (int i = tid; i < 512; i += 64) s[768+i] = px[i];
    }
    __syncthreads();

    int warp = tid >> 5, lane = tid & 31;
    int ch = chunk0 + warp;
    const float4* s  = s4 + warp*1280;
    const float*  sa = (const float*)s;              // a as scalars [t*16+n]
    const float*  sc = (const float*)(s + 512);      // c as scalars [t*16+n]
    const float*  sx = (const float*)(s + 768);      // x [t*32+d]
    int nl = lane & 15;

    float h[16];
    #pragma unroll
    for (int n = 0; n < 16; n++) h[n] = 0.f;
    float pis = 1.f;                                  // prefix prod for n=nl

    float* yout = g_yloc + (size_t)ch*Ll*Dd + lane;
    float* cpio = g_cpi  + (size_t)ch*Ll*Nst;

    #pragma unroll 2
    for (int t = 0; t < Ll; t++) {
        float av[16], bv[16], cv[16];
        *(float4*)&av[0]  = s[t*4+0];     *(float4*)&av[4]  = s[t*4+1];
        *(float4*)&av[8]  = s[t*4+2];     *(float4*)&av[12] = s[t*4+3];
        *(float4*)&bv[0]  = s[256+t*4+0]; *(float4*)&bv[4]  = s[256+t*4+1];
        *(float4*)&bv[8]  = s[256+t*4+2]; *(float4*)&bv[12] = s[256+t*4+3];
        *(float4*)&cv[0]  = s[512+t*4+0]; *(float4*)&cv[4]  = s[512+t*4+1];
        *(float4*)&cv[8]  = s[512+t*4+2]; *(float4*)&cv[12] = s[512+t*4+3];
        float xv = sx[t*32 + lane];

        float y0 = 0.f, y1 = 0.f, y2 = 0.f, y3 = 0.f;
        #pragma unroll
        for (int n = 0; n < 16; n += 4) {
            h[n+0] = fmaf(av[n+0], h[n+0], bv[n+0]*xv); y0 = fmaf(cv[n+0], h[n+0], y0);
            h[n+1] = fmaf(av[n+1], h[n+1], bv[n+1]*xv); y1 = fmaf(cv[n+1], h[n+1], y1);
            h[n+2] = fmaf(av[n+2], h[n+2], bv[n+2]*xv); y2 = fmaf(cv[n+2], h[n+2], y2);
            h[n+3] = fmaf(av[n+3], h[n+3], bv[n+3]*xv); y3 = fmaf(cv[n+3], h[n+3], y3);
        }
        yout[t*Dd] = (y0 + y1) + (y2 + y3);

        // prefix product (per-n scalar in lanes, duplicated in upper half)
        pis *= sa[t*16 + nl];
        if (lane < 16) cpio[t*Nst + lane] = sc[t*16 + lane] * pis;
    }

    float4* outL = (float4*)g_sL + (size_t)ch*128 + lane*4;
    outL[0] = make_float4(h[0],h[1],h[2],h[3]);
    outL[1] = make_float4(h[4],h[5],h[6],h[7]);
    outL[2] = make_float4(h[8],h[9],h[10],h[11]);
    outL[3] = make_float4(h[12],h[13],h[14],h[15]);
    if (lane < 16) g_P[ch*Nst + lane] = pis;
}

// ---------------- K3a: group-local combine; grid 64x4, block 128 ------------
__global__ __launch_bounds__(128) void k3a(void)
{
    int bg   = blockIdx.x >> 2;
    int sub  = blockIdx.x & 3;
    int offg = sub*128 + threadIdx.x;    // 0..511
    int n    = offg & 15;
    int c0   = bg * GL;

    float lp[GL], ls[GL];
    #pragma unroll
    for (int j = 0; j < GL; j++) {
        lp[j] = g_P [(c0+j)*Nst + n];
        ls[j] = g_sL[(size_t)(c0+j)*512 + offg];
    }
    float h = 0.f, pl = 1.f;
    #pragma unroll
    for (int j = 0; j < GL; j++) {
        g_hinL[(size_t)(c0+j)*512 + offg] = h;
        if (offg < 16) g_Plp[(bg*GL + j)*Nst + offg] = pl;
        h  = fmaf(lp[j], h, ls[j]);
        pl *= lp[j];
    }
    g_gend[bg*512 + offg] = h;
    if (offg < 16) g_Pg[bg*Nst + offg] = pl;
}

// ---------------- K3b: cross-group combine + fused per-batch MLP loss -------
__global__ __launch_bounds__(512) void k3b_loss(
    const float* __restrict__ Wd1, const float* __restrict__ bd1,
    const float* __restrict__ Wd2, const float* __restrict__ bd2,
    const float* __restrict__ Wd3, const float* __restrict__ bd3)
{
    __shared__ float sh[512];
    __shared__ float hrep[Nst], z1[HIDn], z2[HIDn], uu[Dd];
    int b = blockIdx.x, off = threadIdx.x, n = off & 15;

    float pg[NGRP], ge[NGRP];
    #pragma unroll
    for (int g = 0; g < NGRP; g++) {
        pg[g] = g_Pg  [(b*NGRP+g)*Nst + n];
        ge[g] = g_gend[(b*NGRP+g)*512 + off];
    }
    float h = 0.f;
    #pragma unroll
    for (int g = 0; g < NGRP; g++) {
        g_Hg[(b*NGRP+g)*512 + off] = h;
        h = fmaf(pg[g], h, ge[g]);
    }
    sh[off] = h;
    __syncthreads();

    if (off < Nst) {
        float s = 0.f;
        #pragma unroll
        for (int d = 0; d < Dd; d++) s += sh[d*Nst + off];
        hrep[off] = s * (1.f/(float)Dd);
    }
    __syncthreads();
    if (off < HIDn) {
        float acc = bd1[off];
        #pragma unroll
        for (int nn = 0; nn < Nst; nn++) acc += hrep[nn] * Wd1[nn*HIDn + off];
        z1[off] = fmaxf(acc, 0.f);
    }
    __syncthreads();
    if (off < HIDn) {
        float acc = bd2[off];
        #pragma unroll 8
        for (int j = 0; j < HIDn; j++) acc += z1[j] * Wd2[j*HIDn + off];
        z2[off] = fmaxf(acc, 0.f);
    }
    __syncthreads();
    if (off < Dd) {
        float acc = bd3[off];
        #pragma unroll 8
        for (int j = 0; j < HIDn; j++) acc += z2[j] * Wd3[j*Dd + off];
        uu[off] = acc;
    }
    __syncthreads();
    if (off == 0) {
        float t1 = 0.f, t2 = 0.f;
        #pragma unroll
        for (int d = 0; d < Dd; d++) {
            t1 += uu[d]*uu[d];
            t2 += uu[d]*g_Sx[b*Dd + d];
        }
        g_lossB[b] = (float)Ss * t1 - 2.f*t2 + g_Sxx[b];
    }
}

// ---------------- K4: token-parallel y + streaming rank-1 expansion ---------
// block = 256, 8 tokens; grid = NCHUNK*8 = 4096 blocks.
__global__ __launch_bounds__(256) void k4_out(
    const float* __restrict__ Wout, const float* __restrict__ bout,
    float* __restrict__ out, long long out_size)
{
    __shared__ float  shin[512];    // composed h_in[d*16+n]
    __shared__ float  scpi[128];    // cpi for 8 tokens [tloc*16+n]
    __shared__ float  sy[256];      // y [tloc*32+d]
    __shared__ float4 sw[8], sb[8];

    int tid = threadIdx.x;
    int ch   = blockIdx.x >> 3;
    int part = blockIdx.x & 7;
    int bg   = ch >> 3, j = ch & 7;

    // compose h_in = hinL + Plp * Hg
    #pragma unroll
    for (int k = 0; k < 2; k++) {
        int i = tid + k*256;
        shin[i] = fmaf(g_Plp[(bg*GL + j)*Nst + (i & 15)],
                       g_Hg[(size_t)bg*512 + i],
                       g_hinL[(size_t)ch*512 + i]);
    }
    if (tid < 128) scpi[tid] = g_cpi[(size_t)ch*1024 + part*128 + tid];
    float yl = g_yloc[(size_t)ch*2048 + part*256 + tid];
    if (tid < 8)       sw[tid]   = ((const float4*)Wout)[tid];
    else if (tid < 16) sb[tid-8] = ((const float4*)bout)[tid-8];
    __syncthreads();

    // y[t,d] = y_local + sum_n cpi[t,n] * h_in[d,n]
    {
        int tloc = tid >> 5, d = tid & 31;
        float y = yl;
        #pragma unroll
        for (int n = 0; n < Nst; n++)
            y = fmaf(scpi[tloc*Nst + n], shin[d*Nst + n], y);
        sy[tid] = y;
    }
    __syncthreads();

    // streaming expansion: 8 tokens * 1024 floats = 2048 float4
    {
        int q = tid & 7, r0 = tid >> 3;
        float4 w4 = sw[q], b4 = sb[q];
        float4* o = (float4*)out + ((size_t)ch*8 + part)*2048;
        #pragma unroll
        for (int k = 0; k < 8; k++) {
            int r = r0 + k*32;
            float y = sy[r];
            float4 v;
            v.x = fmaf(y, w4.x, b4.x);
            v.y = fmaf(y, w4.y, b4.y);
            v.z = fmaf(y, w4.z, b4.z);
            v.w = fmaf(y, w4.w, b4.w);
            __stcs(&o[r*8 + q], v);
        }
    }

    if (blockIdx.x == 0 && tid == 0 && out_size > (long long)OUT_ELEMS) {
        float s = 0.f;
        #pragma unroll
        for (int b = 0; b < Bb; b++) s += g_lossB[b];
        out[out_size - 1] = s * (1.f/(float)(Bb*Ss));
    }
}

// ---------------- launch -----------------------------------------------------
extern "C" void kernel_launch(void* const* d_in, const int* in_sizes, int n_in,
                              void* d_out, int out_size)
{
    const float* x    = (const float*)d_in[0];
    const float* A    = (const float*)d_in[1];
    const float* Win  = (const float*)d_in[2];
    const float* binp = (const float*)d_in[3];
    const float* Wdt  = (const float*)d_in[4];
    const float* bdt  = (const float*)d_in[5];
    const float* Wdtr = (const float*)d_in[6];
    const float* WB   = (const float*)d_in[7];
    const float* WC   = (const float*)d_in[8];
    const float* Wout = (const float*)d_in[9];
    const float* bout = (const float*)d_in[10];
    const float* Wd1  = (const float*)d_in[11];
    const float* bd1  = (const float*)d_in[12];
    const float* Wd2  = (const float*)d_in[13];
    const float* bd2  = (const float*)d_in[14];
    const float* Wd3  = (const float*)d_in[15];
    const float* bd3  = (const float*)d_in[16];
    float* out = (float*)d_out;

    k0_prep  <<<1, 64>>>(Wdt, bdt, Wdtr);
    k1_proj  <<<TOK/8, 256>>>(x, A, Win, binp, WB, WC);
    k2_scan  <<<NCHUNK/2, 64>>>();
    k3a      <<<256, 128>>>();
    k3b_loss <<<Bb, 512>>>(Wd1, bd1, Wd2, bd2, Wd3, bd3);
    k4_out   <<<NCHUNK*8, 256>>>(Wout, bout, out, (long long)out_size);
}